// round 17
// baseline (speedup 1.0000x reference)
// R17: resubmission of R16 (container-level failure; audit clean — 5th
// first-submission broker flake; all four prior resubmits ran fine).
#include <cuda_runtime.h>
#include <cuda_bf16.h>
#include <cstdint>

// ---------------------------------------------------------------- constants
constexpr int B_   = 16;
constexpr int CIN  = 128;
constexpr int H_   = 64;
constexpr int W_   = 64;
constexpr int COUT = 256;
constexpr int HW   = H_ * W_;        // 4096
constexpr int KD   = CIN * 9;        // 1152
constexpr int NPIX = B_ * HW;        // 65536

constexpr int KB16 = KD / 16;        // 72 k16-blocks per plane
constexpr int NCH  = 36;             // k32 chunks
constexpr int NPB  = NPIX / 8;       // 8192 pixel-octets

// ---------------------------------------------------------------- scratch
__device__ __align__(1024) float    g_off[B_ * 18 * HW];
__device__ __align__(1024) uint32_t g_Ahi[KB16 * 16 * 32 * 4];
__device__ __align__(1024) uint32_t g_Alo[KB16 * 16 * 32 * 4];
__device__ __align__(1024) uint32_t g_Bhi[(size_t)KB16 * NPB * 32 * 2];
__device__ __align__(1024) uint32_t g_Blo[(size_t)KB16 * NPB * 32 * 2];

// ---------------------------------------------------------------- helpers
__device__ __forceinline__ uint32_t smem_u32(const void* p) {
    uint32_t a;
    asm("{ .reg .u64 t; cvta.to.shared.u64 t, %1; cvt.u32.u64 %0, t; }" : "=r"(a) : "l"(p));
    return a;
}
#define CPA16(sa, gp) asm volatile("cp.async.cg.shared.global [%0], [%1], 16;" :: "r"(sa), "l"(gp) : "memory")
#define CPA_COMMIT()  asm volatile("cp.async.commit_group;" ::: "memory")

#define LDS128(r0, r1, r2, r3, a) \
    asm volatile("ld.shared.v4.b32 {%0,%1,%2,%3}, [%4];" : "=r"(r0), "=r"(r1), "=r"(r2), "=r"(r3) : "r"(a))
#define LDS64(r0, r1, a) \
    asm volatile("ld.shared.v2.b32 {%0,%1}, [%2];" : "=r"(r0), "=r"(r1) : "r"(a))

#define MMA16816(c, a, b)                                                     \
    asm volatile("mma.sync.aligned.m16n8k16.row.col.f32.bf16.bf16.f32 "       \
        "{%0,%1,%2,%3}, {%4,%5,%6,%7}, {%8,%9}, {%0,%1,%2,%3};"               \
        : "+f"((c)[0]), "+f"((c)[1]), "+f"((c)[2]), "+f"((c)[3])              \
        : "r"((a)[0]), "r"((a)[1]), "r"((a)[2]), "r"((a)[3]),                 \
          "r"((b)[0]), "r"((b)[1]))

__device__ __forceinline__ uint32_t pack_bf2(__nv_bfloat16 lo_k, __nv_bfloat16 hi_k) {
    __nv_bfloat162 t;
    t.x = lo_k;
    t.y = hi_k;
    return *(uint32_t*)&t;
}

// ---------------------------------------------------------------------------
// Kernel 0: weight prep — bf16 hi/lo split, fragment-ready layout, K=tap*128+c
// ---------------------------------------------------------------------------
__global__ void wprep_kernel(const float* __restrict__ w_def)
{
    const int idx = blockIdx.x * blockDim.x + threadIdx.x;
    if (idx >= COUT * KD) return;
    const int o   = idx / KD;
    const int r   = idx % KD;          // c*9 + tap
    const int c   = r / 9;
    const int tap = r % 9;

    const float w = w_def[idx];
    const __nv_bfloat16 hi = __float2bfloat16_rn(w);
    const __nv_bfloat16 lo = __float2bfloat16_rn(w - __bfloat162float(hi));

    const int knew = tap * 128 + c;
    const int kb = knew >> 4, kk = knew & 15;
    const int mb = o >> 4,    mr = o & 15;
    const int lane = (mr & 7) * 4 + ((kk & 7) >> 1);
    const int reg  = (mr >> 3) + ((kk >> 3) << 1);
    const size_t u16i = ((((size_t)kb * 16 + mb) * 32 + lane) * 4 + reg) * 2 + (kk & 1);

    ((unsigned short*)g_Ahi)[u16i] = *(const unsigned short*)&hi;
    ((unsigned short*)g_Alo)[u16i] = *(const unsigned short*)&lo;
}

// ---------------------------------------------------------------------------
// Kernel 1: offset conv — 2 pixels/thread, 256 blocks (all SMs busy)
// ---------------------------------------------------------------------------
__global__ __launch_bounds__(128) void off_conv_kernel(const float* __restrict__ x,
                                                       const float* __restrict__ w_off,
                                                       const float* __restrict__ b_off)
{
    extern __shared__ float sw[];     // 18*1152
    const int tid = threadIdx.x;
    for (int i = tid; i < 18 * KD; i += blockDim.x) sw[i] = w_off[i];
    __syncthreads();

    const int p   = blockIdx.x * blockDim.x + tid;   // 0..32767
    const int b   = p >> 11;
    const int rem = p & 2047;
    const int ho  = rem >> 5;
    const int wo  = (rem & 31) * 2;

    float acc[18][2];
#pragma unroll
    for (int j = 0; j < 18; j++) { acc[j][0] = b_off[j]; acc[j][1] = acc[j][0]; }

    const float* xb = x + (size_t)b * CIN * HW;
    for (int c = 0; c < CIN; c++) {
        const float* xc = xb + c * HW;
        float r[3][4];
#pragma unroll
        for (int dy = 0; dy < 3; dy++) {
            const int iy = ho - 1 + dy;
            const bool vy = (iy >= 0) && (iy < 64);
#pragma unroll
            for (int dx = 0; dx < 4; dx++) {
                const int ix = wo - 1 + dx;
                r[dy][dx] = (vy && ix >= 0 && ix < 64) ? xc[iy * 64 + ix] : 0.0f;
            }
        }
        const float* swc = sw + c * 9;
#pragma unroll
        for (int ky = 0; ky < 3; ky++)
#pragma unroll
            for (int kx = 0; kx < 3; kx++) {
                const float* wp = swc + ky * 3 + kx;
                const float v0 = r[ky][kx];
                const float v1 = r[ky][kx + 1];
#pragma unroll
                for (int j = 0; j < 18; j++) {
                    const float wv = wp[j * KD];
                    acc[j][0] += wv * v0;
                    acc[j][1] += wv * v1;
                }
            }
    }

    float* ob = g_off + (size_t)b * 18 * HW + ho * 64 + wo;
#pragma unroll
    for (int j = 0; j < 18; j++) {
        ob[j * HW]     = acc[j][0];
        ob[j * HW + 1] = acc[j][1];
    }
}

// ---------------------------------------------------------------------------
// Kernel 2: TAP-FUSED bilinear sampling.  Block = 256 pixels x ALL 9 taps x
// all 128 channels.  Tap params (bilinear w + clamped idx) staged in SMEM;
// loop cb(16ch) -> tap -> pr keeps the gather region L1-resident across taps
// (~8x less L2 traffic than one-tap-per-block).  Fragment packing = R6.
// SMEM: float4 sW[2304] (36864B) + ushort4 sI[2304] (18432B) = 55296B
// ---------------------------------------------------------------------------
__global__ __launch_bounds__(256) void sample_kernel(const float* __restrict__ x)
{
    extern __shared__ uint32_t sraw[];
    float4*  sW = (float4*)sraw;
    ushort4* sI = (ushort4*)((char*)sraw + 2304 * 16);

    const int tid = threadIdx.x;
    const int px0 = blockIdx.x * 256;       // global pixel base
    const int b   = px0 >> 12;
    const int hwb = px0 & 4095;             // within-batch base

    // ---- phase 0: per-(px,tap) bilinear weights + indices ----
    for (int e = tid; e < 9 * 256; e += 256) {
        const int tap = e >> 8;
        const int pxl = e & 255;
        const int pix = hwb + pxl;
        const int ho  = pix >> 6;
        const int wo  = pix & 63;

        const float oy = g_off[((size_t)b * 18 + 2 * tap) * HW + pix];
        const float ox = g_off[((size_t)b * 18 + 2 * tap + 1) * HW + pix];

        const float ys = (float)(ho - 1 + (tap / 3)) + oy;
        const float xs = (float)(wo - 1 + (tap % 3)) + ox;

        const float y0f = floorf(ys), x0f = floorf(xs);
        const float wy1 = ys - y0f,  wx1 = xs - x0f;
        const float wy0 = 1.0f - wy1, wx0 = 1.0f - wx1;

        const int y0 = (int)y0f, x0 = (int)x0f;
        const int y1 = y0 + 1,   x1 = x0 + 1;
        const bool vy0 = (y0 >= 0) && (y0 < H_);
        const bool vy1 = (y1 >= 0) && (y1 < H_);
        const bool vx0 = (x0 >= 0) && (x0 < W_);
        const bool vx1 = (x1 >= 0) && (x1 < W_);

        const int y0c = min(max(y0, 0), H_ - 1), y1c = min(max(y1, 0), H_ - 1);
        const int x0c = min(max(x0, 0), W_ - 1), x1c = min(max(x1, 0), W_ - 1);

        sW[e] = make_float4(wy0 * wx0 * ((vy0 && vx0) ? 1.0f : 0.0f),
                            wy0 * wx1 * ((vy0 && vx1) ? 1.0f : 0.0f),
                            wy1 * wx0 * ((vy1 && vx0) ? 1.0f : 0.0f),
                            wy1 * wx1 * ((vy1 && vx1) ? 1.0f : 0.0f));
        sI[e] = make_ushort4((unsigned short)(y0c * 64 + x0c),
                             (unsigned short)(y0c * 64 + x1c),
                             (unsigned short)(y1c * 64 + x0c),
                             (unsigned short)(y1c * 64 + x1c));
    }
    __syncthreads();

    const int gpix  = px0 + tid;
    const int pb    = gpix >> 3;
    const int lanen = (gpix & 7) * 4;
    const float* xb = x + (size_t)b * CIN * HW;

    for (int cb = 0; cb < 8; cb++) {
#pragma unroll 3
        for (int tap = 0; tap < 9; tap++) {
            const int e = tap * 256 + tid;
            const float4  wv = sW[e];
            const ushort4 iv = sI[e];
            const int i00 = iv.x, i01 = iv.y, i10 = iv.z, i11 = iv.w;
            const int kb = tap * 8 + cb;
#pragma unroll
            for (int pr = 0; pr < 4; pr++) {
                const int c0 = cb * 16 + pr * 2;
                const float* xa = xb + c0 * HW;
                float v[4];
#pragma unroll
                for (int u = 0; u < 4; u++) {
                    const float* xc = xa + ((u >> 1) * 8 + (u & 1)) * HW;  // c0, c0+1, c0+8, c0+9
                    v[u] = xc[i00] * wv.x + xc[i01] * wv.y + xc[i10] * wv.z + xc[i11] * wv.w;
                }
                __nv_bfloat16 h[4], l[4];
#pragma unroll
                for (int u = 0; u < 4; u++) {
                    h[u] = __float2bfloat16_rn(v[u]);
                    l[u] = __float2bfloat16_rn(v[u] - __bfloat162float(h[u]));
                }
                const int lane = lanen + pr;
                const size_t base = (((size_t)kb * NPB + pb) * 32 + lane) * 2;
                *(uint2*)&g_Bhi[base] = make_uint2(pack_bf2(h[0], h[1]), pack_bf2(h[2], h[3]));
                *(uint2*)&g_Blo[base] = make_uint2(pack_bf2(l[0], l[1]), pack_bf2(l[2], l[3]));
            }
        }
    }
}

// ---------------------------------------------------------------------------
// Kernel 3: bf16 HMMA GEMM, all 3 terms per k32 chunk.  (R15, proven)
// CTA = m128 x n128, 8 warps.  36 iterations, 3-stage ring, 1 barrier/chunk.
// ---------------------------------------------------------------------------
__global__ __launch_bounds__(256) void gemm_kernel(float* __restrict__ out)
{
    extern __shared__ uint32_t smem[];   // 3 * 8192 u32 = 96 KB

    const int tid  = threadIdx.x;
    const int wid  = tid >> 5;
    const int lane = tid & 31;
    const int mhalf = blockIdx.x;
    const int ntile = blockIdx.y;
    const int mb0 = mhalf * 8;
    const int pb0 = ntile * 16;

    const uint32_t sbase = smem_u32(smem);

    auto load_chunk = [&](int c) {
        const int slot = c % 3;
        const int kb   = c * 2;
        const uint32_t d = sbase + slot * 8192 * 4;
#pragma unroll
        for (int q = 0; q < 2; q++) {
            const uint32_t* asrc_h = g_Ahi + ((size_t)(kb + q) * 16 + mb0) * 128 + tid * 4;
            const uint32_t* asrc_l = g_Alo + ((size_t)(kb + q) * 16 + mb0) * 128 + tid * 4;
            const uint32_t* bsrc_h = g_Bhi + ((size_t)(kb + q) * NPB + pb0) * 64 + tid * 4;
            const uint32_t* bsrc_l = g_Blo + ((size_t)(kb + q) * NPB + pb0) * 64 + tid * 4;
            CPA16(d + (q * 1024 + tid * 4) * 4,        asrc_h);
            CPA16(d + (2048 + q * 1024 + tid * 4) * 4, asrc_l);
            CPA16(d + (4096 + q * 1024 + tid * 4) * 4, bsrc_h);
            CPA16(d + (6144 + q * 1024 + tid * 4) * 4, bsrc_l);
        }
        CPA_COMMIT();
    };

    float acc[4][4][4] = {};

    load_chunk(0);
    load_chunk(1);
    asm volatile("cp.async.wait_group 1;");
    __syncthreads();

    const int wmm = wid >> 2;            // 0..1 -> m64
    const int wnn = wid & 3;             // 0..3 -> n32

    for (int i = 0; i < NCH; i++) {
        if (i + 2 < NCH) load_chunk(i + 2);
        else             CPA_COMMIT();
        asm volatile("cp.async.wait_group 1;");

        const uint32_t sb = sbase + (i % 3) * 8192 * 4;

#pragma unroll
        for (int q = 0; q < 2; q++) {
            uint32_t a[4][4];
            const uint32_t abase = sb + (q * 1024) * 4;
#pragma unroll
            for (int m = 0; m < 4; m++)
                LDS128(a[m][0], a[m][1], a[m][2], a[m][3],
                       abase + ((wmm * 4 + m) * 128 + lane * 4) * 4);
#pragma unroll
            for (int j = 0; j < 4; j++) {
                uint32_t bh[2], bl[2];
                const uint32_t ba = sb + (4096 + q * 1024 + (wnn * 4 + j) * 64 + lane * 2) * 4;
                LDS64(bh[0], bh[1], ba);
                LDS64(bl[0], bl[1], ba + 2048 * 4);
#pragma unroll
                for (int m = 0; m < 4; m++) {
                    MMA16816(acc[m][j], a[m], bh);
                    MMA16816(acc[m][j], a[m], bl);
                }
            }
#pragma unroll
            for (int m = 0; m < 4; m++)
                LDS128(a[m][0], a[m][1], a[m][2], a[m][3],
                       abase + (2048 + (wmm * 4 + m) * 128 + lane * 4) * 4);
#pragma unroll
            for (int j = 0; j < 4; j++) {
                uint32_t bh[2];
                const uint32_t ba = sb + (4096 + q * 1024 + (wnn * 4 + j) * 64 + lane * 2) * 4;
                LDS64(bh[0], bh[1], ba);
#pragma unroll
                for (int m = 0; m < 4; m++)
                    MMA16816(acc[m][j], a[m], bh);
            }
        }
        __syncthreads();
    }

    const int cout_base = mhalf * 128 + wmm * 64;
    const int n_base    = ntile * 128 + wnn * 32;
    const int bidx = n_base >> 12;
    const int hwb  = n_base & 4095;

#pragma unroll
    for (int m = 0; m < 4; m++) {
        const int m0 = cout_base + m * 16 + (lane >> 2);
        float* row1 = out + ((size_t)(bidx * COUT + m0)) * HW + hwb;
        float* row2 = row1 + (size_t)8 * HW;
#pragma unroll
        for (int j = 0; j < 4; j++) {
            const int n0 = j * 8 + (lane & 3) * 2;
            *(float2*)(row1 + n0) = make_float2(acc[m][j][0], acc[m][j][1]);
            *(float2*)(row2 + n0) = make_float2(acc[m][j][2], acc[m][j][3]);
        }
    }
}

// ---------------------------------------------------------------------------
extern "C" void kernel_launch(void* const* d_in, const int* in_sizes, int n_in,
                              void* d_out, int out_size)
{
    const float* x     = (const float*)d_in[0];
    const float* w_off = (const float*)d_in[1];
    const float* b_off = (const float*)d_in[2];
    const float* w_def = (const float*)d_in[3];
    float* out = (float*)d_out;

    const int smem_off = 18 * KD * sizeof(float);        // 82944
    cudaFuncSetAttribute(off_conv_kernel,
                         cudaFuncAttributeMaxDynamicSharedMemorySize, smem_off);
    const int smem_samp = 2304 * 16 + 2304 * 8;          // 55296
    cudaFuncSetAttribute(sample_kernel,
                         cudaFuncAttributeMaxDynamicSharedMemorySize, smem_samp);
    const int smem_gemm = 3 * 8192 * 4;                  // 98304
    cudaFuncSetAttribute(gemm_kernel,
                         cudaFuncAttributeMaxDynamicSharedMemorySize, smem_gemm);

    wprep_kernel<<<(COUT * KD + 255) / 256, 256>>>(w_def);
    off_conv_kernel<<<(NPIX / 2) / 128, 128, smem_off>>>(x, w_off, b_off);
    sample_kernel<<<NPIX / 256, 256, smem_samp>>>(x);
    gemm_kernel<<<dim3(2, NPIX / 128), 256, smem_gemm>>>(out);
}